// round 13
// baseline (speedup 1.0000x reference)
#include <cuda_runtime.h>
#include <cuda_fp16.h>
#include <cstdint>

#define BATCH 4096
#define S_SZ  200
#define D_SZ  256

// ---- K_score dynamic SMEM word map (max NMT=5) ----
#define XH_W     0          // 5*2048 words: X_hi fp16 fragments
#define XL_W     10240      // X_lo fragments
#define SC_W     20480      // 256 f32 combined bias
#define SCORE_W  20736      // 80 f32 row sums / exp values
#define SRED_W   20816      // 20 f32 reduction scratch
#define STAGE_W  20836      // 5120 f32 staging (80 rows x 64 cols), 16B-aligned
#define SMEM_WORDS 25956
#define SMEM_BYTES (SMEM_WORDS * 4)

__device__ float g_catep[BATCH * D_SZ];
__device__ int   g_mask_mode;                 // 0=u8, 1=i32, 2=f32
__device__ uint4 g_w1pk[32 * 16 * 32];        // 256 KB packed fp16 W hi/lo fragments
__device__ float g_pm[BATCH * 3];             // per-third local max
__device__ float g_pl[BATCH * 3];             // per-third local exp-sum
__device__ float g_pp[BATCH * 3 * D_SZ];      // per-third unnormalized pooled partials

__device__ __forceinline__ uint32_t s2u(const void* p) {
    uint32_t a;
    asm("{ .reg .u64 t; cvta.to.shared.u64 t, %1; cvt.u32.u64 %0, t; }" : "=r"(a) : "l"(p));
    return a;
}
__device__ __forceinline__ unsigned pack_hf2(float lo, float hi) {
    unsigned r;
    asm("cvt.rn.f16x2.f32 %0, %1, %2;" : "=r"(r) : "f"(hi), "f"(lo));
    return r;
}
__device__ __forceinline__ float hf_lo(unsigned w) { return __half2float(__ushort_as_half((unsigned short)(w & 0xFFFFu))); }
__device__ __forceinline__ float hf_hi(unsigned w) { return __half2float(__ushort_as_half((unsigned short)(w >> 16))); }
__device__ __forceinline__ float sigf(float x) { return __fdividef(1.0f, 1.0f + __expf(-x)); }

#define MMAF16(d, a0, a1, a2, a3, b0, b1)                                     \
    asm volatile("mma.sync.aligned.m16n8k16.row.col.f32.f16.f16.f32 "         \
                 "{%0,%1,%2,%3}, {%4,%5,%6,%7}, {%8,%9}, {%0,%1,%2,%3};"      \
                 : "+f"(d[0]), "+f"(d[1]), "+f"(d[2]), "+f"(d[3])             \
                 : "r"(a0), "r"(a1), "r"(a2), "r"(a3), "r"(b0), "r"(b1))

#define CP_ASYNC16(dst, src, ss) \
    asm volatile("cp.async.ca.shared.global [%0], [%1], 16, %2;" \
                 :: "r"(dst), "l"(src), "r"(ss) : "memory")
#define CP_COMMIT()  asm volatile("cp.async.commit_group;" ::: "memory")
#define CP_WAIT0()   asm volatile("cp.async.wait_group 0;" ::: "memory")

// ---------------------------------------------------------------------------
// Prep: blocks 0..255 = catep GEMM (fp32 exact), 256 = W1 fp16 hi/lo fragment
// pack, 257 = mask dtype detection.
// ---------------------------------------------------------------------------
__global__ void prep_kernel(const float* __restrict__ cate,
                            const float* __restrict__ W2,
                            const float* __restrict__ b2,
                            const float* __restrict__ W1,
                            const unsigned* __restrict__ mw) {
    __shared__ float sm[16 * 256];
    __shared__ int   fl[2];
    const int blk = blockIdx.x, tid = threadIdx.x;

    if (blk < 256) {
        const int bbase = blk * 16;
        #pragma unroll
        for (int i = 0; i < 16; i++)
            sm[i * 256 + tid] = cate[(size_t)(bbase + i) * 256 + tid];
        __syncthreads();

        float acc[16];
        #pragma unroll
        for (int r = 0; r < 16; r++) acc[r] = 0.0f;
        const float4* w2row = (const float4*)(W2 + (size_t)tid * 256);
        #pragma unroll 8
        for (int k4 = 0; k4 < 64; k4++) {
            const float4 w = w2row[k4];
            #pragma unroll
            for (int r = 0; r < 16; r++) {
                const float4 s4 = *(const float4*)(sm + r * 256 + k4 * 4);
                acc[r] += s4.x * w.x + s4.y * w.y + s4.z * w.z + s4.w * w.w;
            }
        }
        const float bias = b2[tid];
        #pragma unroll
        for (int r = 0; r < 16; r++)
            g_catep[(size_t)(bbase + r) * 256 + tid] = acc[r] + bias;
    } else if (blk == 256) {
        // entry e = (ntg*16 + kt)*32 + lane ; lane = qr*4 + qc
        for (int e = tid; e < 32 * 16 * 32; e += 256) {
            const int ntg = e >> 9, kt = (e >> 5) & 15, lane = e & 31;
            const int qr = lane >> 2, qc = lane & 3;
            const float* src = W1 + (size_t)(ntg * 8 + qr) * 256 + kt * 16 + 2 * qc;
            const float w0 = src[0], w1v = src[1], w8 = src[8], w9 = src[9];
            const unsigned h0 = pack_hf2(w0, w1v);
            const unsigned h1 = pack_hf2(w8, w9);
            const float2 f0 = __half22float2(*(const __half2*)&h0);
            const float2 f1 = __half22float2(*(const __half2*)&h1);
            const unsigned l0 = pack_hf2(w0 - f0.x, w1v - f0.y);
            const unsigned l1 = pack_hf2(w8 - f1.x, w9 - f1.y);
            g_w1pk[e] = make_uint4(h0, h1, l0, l1);
        }
    } else {
        if (tid == 0) { fl[0] = 0; fl[1] = 0; }
        __syncthreads();
        int lF = 0, lU = 0;
        for (int i = tid; i < 4096; i += 256) {
            const unsigned v = mw[i];
            if (v == 0x3F800000u) lF = 1;
            if (v & 0xFFFFFF00u)  lU = 1;
        }
        if (lF) fl[0] = 1;
        if (lU) fl[1] = 1;
        __syncthreads();
        if (tid == 0) g_mask_mode = fl[0] ? 2 : (fl[1] ? 0 : 1);
    }
}

// ---------------------------------------------------------------------------
// Pipelined score body: cp.async stages X in 4 k-slices of 64 cols; slice
// sl+1 streams while slice sl's MMAs run. 3-term fp16 GEMM, then local
// masked softmax + unnormalized pooled partial (flash-style two-level).
// ---------------------------------------------------------------------------
template <int NMT>
__device__ __forceinline__ void score_body(const float* __restrict__ seq,
                                           const void*  __restrict__ maskp,
                                           const float* __restrict__ b1,
                                           int b, int third, int r0) {
    extern __shared__ unsigned sw[];
    const uint32_t sb = s2u(sw);
    const int nr  = NMT * 16;
    const int tid = threadIdx.x, warp = tid >> 5, lane = tid & 31;
    const int qr = lane >> 2, qc = lane & 3;

    float* sC     = (float*)(sw + SC_W);
    float* sScore = (float*)(sw + SCORE_W);
    float* sRed   = (float*)(sw + SRED_W);
    const float* stage = (const float*)(sw + STAGE_W);
    const float* seqb  = seq + (size_t)b * S_SZ * D_SZ;

    // ---- issue slice 0 immediately ----
    const int nfl = nr * 16;                 // float4s per slice
    {
        for (int i = tid; i < nfl; i += 256) {
            const int lr = i >> 4, c4g = i & 15;
            const int g = r0 + lr;
            const int ok = (g < S_SZ);
            const float* src = seqb + (size_t)(ok ? g : 0) * 256 + c4g * 4;
            CP_ASYNC16(sb + (STAGE_W + lr * 64 + c4g * 4) * 4, src, ok ? 16 : 0);
        }
        CP_COMMIT();
    }

    // ---- early mask load + bias setup (overlaps cp.async) ----
    bool mk = true;
    if (tid < nr) {
        const int s = r0 + tid;
        if (s < S_SZ) {
            const size_t mi = (size_t)b * S_SZ + s;
            const int mode = g_mask_mode;
            if (mode == 0)      mk = ((const unsigned char*)maskp)[mi] != 0;
            else if (mode == 1) mk = ((const int*)maskp)[mi] != 0;
            else                mk = ((const float*)maskp)[mi] != 0.0f;
        }
    }
    sC[tid] = g_catep[(size_t)b * 256 + tid] + b1[tid];
    if (tid < 80) sScore[tid] = 0.0f;

    // ---- GEMM state ----
    const int n0   = warp * 32;
    const int ntg0 = n0 >> 3;
    float acc[NMT][4][4];
    #pragma unroll
    for (int mt = 0; mt < NMT; mt++)
        #pragma unroll
        for (int j = 0; j < 4; j++)
            #pragma unroll
            for (int i = 0; i < 4; i++) acc[mt][j][i] = 0.0f;

    uint4 wq[4];
    #pragma unroll
    for (int j = 0; j < 4; j++)
        wq[j] = g_w1pk[(size_t)((ntg0 + j) * 16) * 32 + lane];

    CP_WAIT0();
    __syncthreads();                         // slice 0 staged

    #pragma unroll 1
    for (int sl = 0; sl < 4; sl++) {
        // ---- convert slice sl: stage -> fp16 hi/lo fragments ----
        for (int i = tid; i < nfl; i += 256) {
            const int lr = i >> 4, c4l = i & 15;
            const float4 v = *(const float4*)(stage + lr * 64 + c4l * 4);
            const unsigned h01 = pack_hf2(v.x, v.y);
            const unsigned h23 = pack_hf2(v.z, v.w);
            const float2 f01 = __half22float2(*(const __half2*)&h01);
            const float2 f23 = __half22float2(*(const __half2*)&h23);
            const unsigned l01 = pack_hf2(v.x - f01.x, v.y - f01.y);
            const unsigned l23 = pack_hf2(v.z - f23.x, v.w - f23.y);
            const int c4 = sl * 16 + c4l;
            const int cp = 2 * c4, rr = cp & 7;
            const int r16 = lr & 15;
            const int widx = (lr >> 4) * 2048 + (cp >> 3) * 128
                           + (r16 & 7) * 16 + (rr & 3) * 4 + (rr >> 2) * 2 + (r16 >> 3);
            sw[XH_W + widx]     = h01;
            sw[XH_W + widx + 4] = h23;
            sw[XL_W + widx]     = l01;
            sw[XL_W + widx + 4] = l23;
        }
        __syncthreads();                     // frags ready; stage consumed

        // ---- issue cp.async for slice sl+1 (overlaps MMAs below) ----
        if (sl < 3) {
            for (int i = tid; i < nfl; i += 256) {
                const int lr = i >> 4, c4g = i & 15;
                const int g = r0 + lr;
                const int ok = (g < S_SZ);
                const float* src = seqb + (size_t)(ok ? g : 0) * 256
                                 + (sl + 1) * 64 + c4g * 4;
                CP_ASYNC16(sb + (STAGE_W + lr * 64 + c4g * 4) * 4, src, ok ? 16 : 0);
            }
            CP_COMMIT();
        }

        // ---- MMAs for the 4 k-tiles of this slice ----
        #pragma unroll
        for (int ktl = 0; ktl < 4; ktl++) {
            const int kt = sl * 4 + ktl;
            uint4 w[4];
            #pragma unroll
            for (int j = 0; j < 4; j++) w[j] = wq[j];
            if (kt < 15) {
                #pragma unroll
                for (int j = 0; j < 4; j++)
                    wq[j] = g_w1pk[(size_t)((ntg0 + j) * 16 + kt + 1) * 32 + lane];
            }
            const unsigned abase = kt * 128 + lane * 4;
            #pragma unroll
            for (int mt = 0; mt < NMT; mt++) {
                const uint4 ah = *(const uint4*)(sw + XH_W + mt * 2048 + abase);
                const uint4 al = *(const uint4*)(sw + XL_W + mt * 2048 + abase);
                #pragma unroll
                for (int j = 0; j < 4; j++)
                    MMAF16(acc[mt][j], ah.x, ah.y, ah.z, ah.w, w[j].x, w[j].y);
                #pragma unroll
                for (int j = 0; j < 4; j++)
                    MMAF16(acc[mt][j], al.x, al.y, al.z, al.w, w[j].x, w[j].y);
                #pragma unroll
                for (int j = 0; j < 4; j++)
                    MMAF16(acc[mt][j], ah.x, ah.y, ah.z, ah.w, w[j].z, w[j].w);
            }
        }

        if (sl < 3) {
            CP_WAIT0();
            __syncthreads();                 // slice sl+1 staged
        }
    }

    // ---- epilogue: sigmoid + per-row partial sums -> smem atomics ----
    {
        float b0[4], b1v[4];
        #pragma unroll
        for (int j = 0; j < 4; j++) {
            b0[j]  = sC[n0 + j * 8 + 2 * qc];
            b1v[j] = sC[n0 + j * 8 + 2 * qc + 1];
        }
        #pragma unroll
        for (int mt = 0; mt < NMT; mt++) {
            float v0 = 0.0f, v1 = 0.0f;
            #pragma unroll
            for (int j = 0; j < 4; j++) {
                v0 += sigf(acc[mt][j][0] + b0[j]) + sigf(acc[mt][j][1] + b1v[j]);
                v1 += sigf(acc[mt][j][2] + b0[j]) + sigf(acc[mt][j][3] + b1v[j]);
            }
            v0 += __shfl_xor_sync(0xffffffffu, v0, 1);
            v0 += __shfl_xor_sync(0xffffffffu, v0, 2);
            v1 += __shfl_xor_sync(0xffffffffu, v1, 1);
            v1 += __shfl_xor_sync(0xffffffffu, v1, 2);
            if (qc == 0) {
                atomicAdd(&sScore[mt * 16 + qr], v0);
                atomicAdd(&sScore[mt * 16 + qr + 8], v1);
            }
        }
    }
    __syncthreads();

    // ---- local masked softmax over nr rows ----
    float sv = (tid < nr) ? (mk ? -1e9f : sScore[tid]) : -3.4e38f;

    float m = sv;
    #pragma unroll
    for (int o = 16; o > 0; o >>= 1) m = fmaxf(m, __shfl_xor_sync(0xffffffffu, m, o));
    if (lane == 0) sRed[warp] = m;
    __syncthreads();
    if (warp == 0) {
        float t = (lane < 8) ? sRed[lane] : -3.4e38f;
        #pragma unroll
        for (int o = 16; o > 0; o >>= 1) t = fmaxf(t, __shfl_xor_sync(0xffffffffu, t, o));
        if (lane == 0) sRed[16] = t;
    }
    __syncthreads();
    m = sRed[16];

    const float ev = (tid < nr) ? __expf(sv - m) : 0.0f;
    float l = ev;
    #pragma unroll
    for (int o = 16; o > 0; o >>= 1) l += __shfl_xor_sync(0xffffffffu, l, o);
    if (lane == 0) sRed[warp] = l;
    __syncthreads();
    if (warp == 0) {
        float u = (lane < 8) ? sRed[lane] : 0.0f;
        #pragma unroll
        for (int o = 16; o > 0; o >>= 1) u += __shfl_xor_sync(0xffffffffu, u, o);
        if (lane == 0) sRed[17] = u;
    }
    __syncthreads();                 // sScore reads done; sRed[17] final
    if (tid < nr) sScore[tid] = ev;
    __syncthreads();

    // ---- unnormalized pooled partial from SMEM X (x = hi + lo) ----
    {
        const int cp = tid >> 1, hl = tid & 1;
        const int Cd = (cp >> 3) * 128 + (cp & 3) * 4 + ((cp & 7) >> 2) * 2;
        float accd = 0.0f;
        #pragma unroll 4
        for (int s = 0; s < nr; s++) {
            const int fs = (s >> 4) * 2048 + (s & 7) * 16 + ((s & 15) >> 3);
            const unsigned wh = sw[XH_W + Cd + fs];
            const unsigned wl = sw[XL_W + Cd + fs];
            const float x = (hl ? hf_hi(wh) : hf_lo(wh)) + (hl ? hf_hi(wl) : hf_lo(wl));
            accd += sScore[s] * x;
        }
        g_pp[(size_t)(b * 3 + third) * 256 + tid] = accd;
        if (tid == 0) {
            g_pm[b * 3 + third] = m;
            g_pl[b * 3 + third] = sRed[17];
        }
    }
}

// ---------------------------------------------------------------------------
// K_score: 3 CTAs per batch (rows 0-79 / 80-143 / 144-207).
// ---------------------------------------------------------------------------
__global__ void __launch_bounds__(256, 2)
score_kernel(const float* __restrict__ seq,
             const void*  __restrict__ maskp,
             const float* __restrict__ b1) {
    const int bid = blockIdx.x;
    const int b = bid / 3, third = bid - 3 * b;
    if (third == 0) score_body<5>(seq, maskp, b1, b, 0, 0);
    else if (third == 1) score_body<4>(seq, maskp, b1, b, 1, 80);
    else score_body<4>(seq, maskp, b1, b, 2, 144);
}

// ---------------------------------------------------------------------------
// K_combine: merge the 3 thirds -- global max, rescale, normalize.
// ---------------------------------------------------------------------------
__global__ void __launch_bounds__(256)
combine_kernel(float* __restrict__ out) {
    const int b = blockIdx.x, tid = threadIdx.x;
    const float m0 = g_pm[b * 3], m1 = g_pm[b * 3 + 1], m2 = g_pm[b * 3 + 2];
    const float m  = fmaxf(m0, fmaxf(m1, m2));
    const float w0 = __expf(m0 - m), w1 = __expf(m1 - m), w2 = __expf(m2 - m);
    const float L  = w0 * g_pl[b * 3] + w1 * g_pl[b * 3 + 1] + w2 * g_pl[b * 3 + 2];
    const float inv = 1.0f / L;
    const float p = w0 * g_pp[(size_t)(b * 3) * 256 + tid]
                  + w1 * g_pp[(size_t)(b * 3 + 1) * 256 + tid]
                  + w2 * g_pp[(size_t)(b * 3 + 2) * 256 + tid];
    out[(size_t)b * 256 + tid] = p * inv;
}

// ---------------------------------------------------------------------------
extern "C" void kernel_launch(void* const* d_in, const int* in_sizes, int n_in,
                              void* d_out, int out_size) {
    const float* cate = (const float*)d_in[0];
    const float* seq  = (const float*)d_in[1];
    const void*  mask = d_in[2];
    const float* W1   = (const float*)d_in[3];
    const float* b1   = (const float*)d_in[4];
    const float* W2   = (const float*)d_in[5];
    const float* b2   = (const float*)d_in[6];
    float*       out  = (float*)d_out;

    cudaFuncSetAttribute(score_kernel,
                         cudaFuncAttributeMaxDynamicSharedMemorySize, SMEM_BYTES);

    prep_kernel<<<258, 256>>>(cate, W2, b2, W1, (const unsigned*)mask);
    score_kernel<<<3 * BATCH, 256, SMEM_BYTES>>>(seq, mask, b1);
    combine_kernel<<<BATCH, 256>>>(out);
}